// round 15
// baseline (speedup 1.0000x reference)
#include <cuda_runtime.h>
#include <cuda_bf16.h>
#include <math.h>
#include <stdint.h>

#define BB 32
#define TT 100
#define NN 150
#define CHN 32
#define HID1 512
#define RHID2 150
#define DIN (NN*CHN)        // 4800
#define G1 (3*HID1)         // 1536
#define G2 (3*RHID2)        // 450
#define ROWS (BB*TT)        // 3200
#define TOPK 10
#define DECS 152
#define NB1 128
#define KSPLIT 2
#define CH_PER 75

typedef unsigned long long u64;

// ---------------- scratch ----------------
__device__ __align__(256) float g_Mt[NN*NN];
__device__ __align__(256) __nv_bfloat16 g_Ahi[(size_t)ROWS*DIN];
__device__ __align__(256) __nv_bfloat16 g_Alo[(size_t)ROWS*DIN];
__device__ __align__(256) __nv_bfloat16 g_Bhi[(size_t)G1*DIN];
__device__ __align__(256) __nv_bfloat16 g_Blo[(size_t)G1*DIN];
__device__ __align__(256) float g_xi1a[(size_t)ROWS*G1];
__device__ __align__(256) float g_xi1b[(size_t)ROWS*G1];
__device__ __align__(256) float g_h[2*BB*HID1];
__device__ __align__(256) float g_P[(HID1+1)*G2];
__device__ __align__(256) float g_xi2[(size_t)ROWS*G2];
__device__ __align__(256) float g_dec[(size_t)ROWS*DECS];
__device__ __align__(256) float g_WfcP[NN*DECS];
__device__ int g_cnt1;
__device__ volatile int g_rel1[NB1*8];

__device__ __forceinline__ uint32_t smem_u32(const void* p) {
    uint32_t a;
    asm("{ .reg .u64 t; cvta.to.shared.u64 t, %1; cvt.u32.u64 %0, t; }" : "=r"(a) : "l"(p));
    return a;
}
__device__ __forceinline__ void ldsm_x4(uint32_t* r, uint32_t addr) {
    asm volatile("ldmatrix.sync.aligned.m8n8.x4.shared.b16 {%0,%1,%2,%3}, [%4];"
        : "=r"(r[0]), "=r"(r[1]), "=r"(r[2]), "=r"(r[3]) : "r"(addr));
}
__device__ __forceinline__ void mma16816(float* c, const uint32_t* a, const uint32_t* b) {
    asm volatile("mma.sync.aligned.m16n8k16.row.col.f32.bf16.bf16.f32 "
        "{%0,%1,%2,%3}, {%4,%5,%6,%7}, {%8,%9}, {%0,%1,%2,%3};"
        : "+f"(c[0]), "+f"(c[1]), "+f"(c[2]), "+f"(c[3])
        : "r"(a[0]), "r"(a[1]), "r"(a[2]), "r"(a[3]), "r"(b[0]), "r"(b[1]));
}
__device__ __forceinline__ uint32_t sw64(uint32_t off) {
    return off ^ ((off >> 3) & 0x30);
}
__device__ __forceinline__ void cp16(uint32_t s, const void* g) {
    asm volatile("cp.async.cg.shared.global [%0], [%1], 16;" :: "r"(s), "l"(g));
}
#define CP_COMMIT() asm volatile("cp.async.commit_group;" ::: "memory")
#define CP_WAIT(n)  asm volatile("cp.async.wait_group %0;" :: "n"(n) : "memory")
__device__ __forceinline__ void ffma2(u64& d, u64 a, u64 b) {
    asm("fma.rn.f32x2 %0, %1, %2, %0;" : "+l"(d) : "l"(a), "l"(b));
}
__device__ __forceinline__ float unpack_sum(u64 v) {
    float x, y;
    asm("mov.b64 {%0,%1}, %2;" : "=f"(x), "=f"(y) : "l"(v));
    return x + y;
}

// ---------------- graph construction (512 threads, 16 topk warps) ----------------
__global__ void k_graph(const float* __restrict__ emb, float* __restrict__ Mt) {
    __shared__ float Wn[NN][CHN];
    __shared__ float rowbuf[16][NN+2];
    __shared__ int   eidx[NN*TOPK];
    __shared__ float eval_[NN*TOPK];
    __shared__ float deg[NN];
    __shared__ float dinv[NN];
    int tid = threadIdx.x;
    for (int i = tid; i < NN; i += blockDim.x) {
        float s = 0.f;
        for (int c = 0; c < CHN; c++) { float v = emb[i*CHN+c]; s += v*v; }
        float inv = 1.f/fmaxf(sqrtf(s), 1e-8f);
        for (int c = 0; c < CHN; c++) Wn[i][c] = emb[i*CHN+c]*inv;
    }
    for (int i = tid; i < NN; i += blockDim.x) deg[i] = 0.f;
    __syncthreads();
    int w = tid >> 5, l = tid & 31;
    for (int i = w; i < NN; i += 16) {
        for (int j = l; j < NN; j += 32) {
            float s = 0.f;
            #pragma unroll
            for (int c = 0; c < CHN; c++) s += Wn[i][c]*Wn[j][c];
            if (j == i) s = 0.f;
            rowbuf[w][j] = fmaxf(s, 0.f);
        }
        __syncwarp();
        for (int rep = 0; rep < TOPK; rep++) {
            float bv = -2.f; int bi = 1<<30;
            for (int j = l; j < NN; j += 32) {
                float v = rowbuf[w][j];
                if (v > bv) { bv = v; bi = j; }
            }
            for (int off = 16; off; off >>= 1) {
                float ov = __shfl_down_sync(0xffffffffu, bv, off);
                int   oi = __shfl_down_sync(0xffffffffu, bi, off);
                if (ov > bv || (ov == bv && oi < bi)) { bv = ov; bi = oi; }
            }
            bv = __shfl_sync(0xffffffffu, bv, 0);
            bi = __shfl_sync(0xffffffffu, bi, 0);
            if (l == 0) {
                eidx[i*TOPK+rep] = bi;
                eval_[i*TOPK+rep] = bv;
                rowbuf[w][bi] = -1.f;
            }
            __syncwarp();
        }
    }
    __syncthreads();
    for (int e = tid; e < NN*TOPK; e += blockDim.x)
        atomicAdd(&deg[eidx[e]], eval_[e]);
    __syncthreads();
    for (int i = tid; i < NN; i += blockDim.x)
        dinv[i] = deg[i] > 0.f ? 1.f/sqrtf(deg[i]) : 0.f;
    for (int i = tid; i < NN*NN; i += blockDim.x) Mt[i] = 0.f;
    __syncthreads();
    for (int e = tid; e < NN*TOPK; e += blockDim.x) {
        int src = e / TOPK;
        int dst = eidx[e];
        Mt[src*NN + dst] = dinv[src]*eval_[e]*dinv[dst];
    }
}

// ---------------- ARMA conv + gelu + emb -> bf16 hi/lo (perm fused in) --------------
__global__ void k_arma(const float* __restrict__ window, const float* __restrict__ emb,
                       const float* __restrict__ w_init, const float* __restrict__ w_root,
                       const float* __restrict__ arma_b, const float* __restrict__ Mt,
                       __nv_bfloat16* __restrict__ Ahi, __nv_bfloat16* __restrict__ Alo) {
    __shared__ float xs[NN];
    __shared__ float s[NN];
    __shared__ int rowbase[NN];
    __shared__ int embbase[NN];
    int blk = blockIdx.x;
    int base = blk*NN;
    int tid = threadIdx.x;
    for (int i = tid; i < NN; i += blockDim.x) {
        int f = base + i;
        int bx  = f / (NN*TT);
        int rem = f - bx*(NN*TT);
        int nx  = rem / TT;
        int tx2 = rem - nx*TT;
        xs[i] = window[(bx*TT + tx2)*NN + nx];
        rowbase[i] = (bx*TT + tx2)*DIN + nx*CHN;
        embbase[i] = nx*CHN;
    }
    __syncthreads();
    for (int n = tid; n < NN; n += blockDim.x) {
        float acc = 0.f;
        #pragma unroll 5
        for (int m = 0; m < NN; m++) acc += Mt[m*NN+n]*xs[m];
        s[n] = acc;
    }
    __syncthreads();
    for (int i = tid; i < DIN; i += blockDim.x) {
        int n = i >> 5, c = i & 31;
        float v = s[n]*w_init[c] + xs[n]*w_root[c] + arma_b[c];
        float g = 0.5f*v*(1.f + erff(v*0.70710678118654752f));
        float val = g + emb[embbase[n] + c];
        __nv_bfloat16 hi = __float2bfloat16(val);
        float lo = val - __bfloat162float(hi);
        size_t idx = (size_t)rowbase[n] + c;
        Ahi[idx] = hi;
        Alo[idx] = __float2bfloat16(lo);
    }
}

// ---------------- Wi1 fp32 -> bf16 hi/lo split ----------------
__global__ void k_convW(const float* __restrict__ Wi1,
                        __nv_bfloat16* __restrict__ Bhi, __nv_bfloat16* __restrict__ Blo) {
    size_t i = (size_t)blockIdx.x*blockDim.x + threadIdx.x;
    if (i >= (size_t)G1*DIN) return;
    float v = Wi1[i];
    __nv_bfloat16 hi = __float2bfloat16(v);
    Bhi[i] = hi;
    Blo[i] = __float2bfloat16(v - __bfloat162float(hi));
}

// ---------------- mma.sync bf16-split GEMM: split-K x2, plain stores per half ------
__global__ void __launch_bounds__(256, 2) gemm_mma(
    const __nv_bfloat16* __restrict__ Ahi, const __nv_bfloat16* __restrict__ Alo,
    const __nv_bfloat16* __restrict__ Bhi, const __nv_bfloat16* __restrict__ Blo,
    float* __restrict__ C0, float* __restrict__ C1) {
    extern __shared__ char dsm[];
    int tid = threadIdx.x, wid = tid >> 5, lane = tid & 31;
    int bm = blockIdx.y*128, bn = blockIdx.x*128;
    int cbeg = blockIdx.z*CH_PER;
    int wm = (wid & 3)*32;
    int wn = (wid >> 2)*64;

    uint32_t dbase = smem_u32(dsm);
    uint32_t pad = (1024u - (dbase & 1023u)) & 1023u;
    uint32_t tb = dbase + pad;

    float acc[2][8][4];
    #pragma unroll
    for (int i = 0; i < 2; i++)
        #pragma unroll
        for (int j = 0; j < 8; j++)
            #pragma unroll
            for (int q = 0; q < 4; q++) acc[i][j][q] = 0.f;

    int a_row = (lane & 15);
    int a_kc  = (lane >= 16) ? 8 : 0;
    int b_n   = (lane & 7) + ((lane & 16) ? 8 : 0);
    int b_kc  = (lane & 8) ? 8 : 0;

    int l_row[2], l_q[2];
    #pragma unroll
    for (int it = 0; it < 2; ++it) {
        int idx = it*256 + tid;
        l_row[it] = idx >> 2;
        l_q[it]   = idx & 3;
    }

    #define LOAD_STAGE(ca, s) do {                                         \
        uint32_t sb_ = tb + (s)*32768;                                     \
        int c0_ = (ca)*32;                                                 \
        _Pragma("unroll")                                                  \
        for (int it = 0; it < 2; ++it) {                                   \
            uint32_t sw_ = sw64(l_row[it]*64 + l_q[it]*16);                \
            size_t ga_ = (size_t)(bm + l_row[it])*DIN + c0_ + l_q[it]*8;   \
            size_t gb_ = (size_t)(bn + l_row[it])*DIN + c0_ + l_q[it]*8;   \
            cp16(sb_ + sw_,         Ahi + ga_);                            \
            cp16(sb_ + 8192 + sw_,  Alo + ga_);                            \
            cp16(sb_ + 16384 + sw_, Bhi + gb_);                            \
            cp16(sb_ + 24576 + sw_, Blo + gb_);                            \
        }                                                                  \
        CP_COMMIT();                                                       \
    } while (0)

    LOAD_STAGE(cbeg + 0, 0);
    LOAD_STAGE(cbeg + 1, 1);
    for (int c = 0; c < CH_PER; ++c) {
        if (c + 2 < CH_PER) { LOAD_STAGE(cbeg + c + 2, (c+2)%3); CP_WAIT(2); }
        else if (c + 1 < CH_PER) CP_WAIT(1);
        else CP_WAIT(0);
        __syncthreads();
        uint32_t sb = tb + (c%3)*32768;
        uint32_t apass[3] = { sb, sb, sb + 8192 };
        uint32_t bpass[3] = { sb + 16384, sb + 24576, sb + 16384 };
        #pragma unroll
        for (int p = 0; p < 3; ++p) {
            uint32_t aT = apass[p], bT = bpass[p];
            #pragma unroll
            for (int ks = 0; ks < 2; ++ks) {
                uint32_t af[2][4];
                #pragma unroll
                for (int mh = 0; mh < 2; ++mh) {
                    int row = wm + mh*16 + a_row;
                    int kc = ks*16 + a_kc;
                    ldsm_x4(af[mh], aT + sw64(row*64 + kc*2));
                }
                uint32_t bf[4][4];
                #pragma unroll
                for (int q = 0; q < 4; ++q) {
                    int n = wn + q*16 + b_n;
                    int kc = ks*16 + b_kc;
                    ldsm_x4(bf[q], bT + sw64(n*64 + kc*2));
                }
                #pragma unroll
                for (int mh = 0; mh < 2; ++mh)
                    #pragma unroll
                    for (int q = 0; q < 4; ++q) {
                        mma16816(acc[mh][2*q],   af[mh], &bf[q][0]);
                        mma16816(acc[mh][2*q+1], af[mh], &bf[q][2]);
                    }
            }
        }
        __syncthreads();
    }

    float* C = blockIdx.z ? C1 : C0;
    #pragma unroll
    for (int mh = 0; mh < 2; ++mh) {
        int row = bm + wm + mh*16 + (lane >> 2);
        #pragma unroll
        for (int nb = 0; nb < 8; ++nb) {
            int col = bn + wn + nb*8 + (lane & 3)*2;
            float* cp = C + (size_t)row*G1 + col;
            cp[0] = acc[mh][nb][0];
            cp[1] = acc[mh][nb][1];
            float* cp2 = cp + 8*G1;
            cp2[0] = acc[mh][nb][2];
            cp2[1] = acc[mh][nb][3];
        }
    }
}

// ---------------- generic SIMT NT GEMM (final fc) ----------------
__global__ void gemm_nt_bias(const float* __restrict__ A, const float* __restrict__ Bm,
                             const float* __restrict__ bias, float* __restrict__ C,
                             int M, int N, int K, int lda, int ldb, int ldc) {
    __shared__ float As[16][132];
    __shared__ float Bs[16][132];
    const int tid = threadIdx.x;
    const int tx = tid & 15, ty = tid >> 4;
    const int bm = blockIdx.y * 128, bn = blockIdx.x * 128;
    float acc[8][8];
    #pragma unroll
    for (int i = 0; i < 8; i++)
        #pragma unroll
        for (int j = 0; j < 8; j++) acc[i][j] = 0.f;
    for (int k0 = 0; k0 < K; k0 += 16) {
        #pragma unroll
        for (int q = 0; q < 2; q++) {
            int idx = tid + q*256;
            int row = idx >> 2;
            int c4  = (idx & 3) << 2;
            int gk = k0 + c4;
            float4 va = make_float4(0.f,0.f,0.f,0.f);
            float4 vb = make_float4(0.f,0.f,0.f,0.f);
            int ga = bm + row, gb = bn + row;
            if (ga < M && gk < K) {
                const float* p = A + (size_t)ga*lda;
                if (gk + 3 < K) va = *(const float4*)(p + gk);
                else {
                    va.x = p[gk];
                    if (gk+1 < K) va.y = p[gk+1];
                    if (gk+2 < K) va.z = p[gk+2];
                }
            }
            if (gb < N && gk < K) {
                const float* p = Bm + (size_t)gb*ldb;
                if (gk + 3 < K) vb = *(const float4*)(p + gk);
                else {
                    vb.x = p[gk];
                    if (gk+1 < K) vb.y = p[gk+1];
                    if (gk+2 < K) vb.z = p[gk+2];
                }
            }
            As[c4+0][row]=va.x; As[c4+1][row]=va.y; As[c4+2][row]=va.z; As[c4+3][row]=va.w;
            Bs[c4+0][row]=vb.x; Bs[c4+1][row]=vb.y; Bs[c4+2][row]=vb.z; Bs[c4+3][row]=vb.w;
        }
        __syncthreads();
        #pragma unroll
        for (int kk = 0; kk < 16; kk++) {
            float4 a0 = *(const float4*)&As[kk][ty*4];
            float4 a1 = *(const float4*)&As[kk][64 + ty*4];
            float4 b0 = *(const float4*)&Bs[kk][tx*4];
            float4 b1 = *(const float4*)&Bs[kk][64 + tx*4];
            float a[8] = {a0.x,a0.y,a0.z,a0.w,a1.x,a1.y,a1.z,a1.w};
            float b[8] = {b0.x,b0.y,b0.z,b0.w,b1.x,b1.y,b1.z,b1.w};
            #pragma unroll
            for (int i = 0; i < 8; i++)
                #pragma unroll
                for (int j = 0; j < 8; j++) acc[i][j] += a[i]*b[j];
        }
        __syncthreads();
    }
    #pragma unroll
    for (int i = 0; i < 8; i++) {
        int gm = bm + ((i < 4) ? ty*4+i : 64+ty*4+(i-4));
        if (gm >= M) continue;
        #pragma unroll
        for (int j = 0; j < 8; j++) {
            int gn = bn + ((j < 4) ? tx*4+j : 64+tx*4+(j-4));
            if (gn < N) C[(size_t)gm*ldc + gn] = acc[i][j] + bias[gn];
        }
    }
}

// ---------------- persistent GRU1: reads xa+xb, biases folded ----------------
__global__ void __launch_bounds__(128) gru1_persist(
    const float* __restrict__ xia, const float* __restrict__ xib,
    const float* __restrict__ Wh1, const float* __restrict__ bi1,
    const float* __restrict__ bh1, float* __restrict__ h0, float* __restrict__ h1) {
    extern __shared__ float sm[];
    float* ws = sm;
    float* hs = sm + 4*3*HID1;
    const int STR = 516;
    int tid = threadIdx.x, w = tid >> 5, l = tid & 31, blk = blockIdx.x;
    int j = blk*4 + w;

    for (int g = 0; g < 3; ++g) {
        const float* src = Wh1 + ((size_t)(g*HID1 + j))*HID1;
        for (int k = l*4; k < HID1; k += 128)
            *(float4*)&ws[(w*3+g)*HID1 + k] = *(const float4*)(src + k);
    }
    float cr = bi1[j] + bh1[j];                       // r-gate total bias
    float cz = bi1[HID1+j] + bh1[HID1+j];             // z-gate total bias
    float bin = bi1[2*HID1+j];                        // n-gate input bias (outside r*)
    float bhn = bh1[2*HID1+j];                        // n-gate hidden bias (inside r*)
    __syncthreads();

    float* hb[2] = { h0, h1 };
    for (int t = 0; t < TT; ++t) {
        const float* hin = hb[t & 1];
        float* hout = hb[(t+1) & 1];
        for (int i = tid; i < BB*(HID1/4); i += 128) {
            int b = i >> 7, k4 = (i & 127) << 2;
            float4 v = __ldcg((const float4*)(hin + b*HID1 + k4));
            *(float4*)&hs[b*STR + k4] = v;
        }
        __syncthreads();
        const float* wr = &ws[(w*3+0)*HID1];
        const float* wz = &ws[(w*3+1)*HID1];
        const float* wn = &ws[(w*3+2)*HID1];
        const float* hp = &hs[l*STR];
        u64 sr0 = 0, sr1 = 0, sz0 = 0, sz1 = 0, sn0 = 0, sn1 = 0;
        #pragma unroll 8
        for (int k = 0; k < HID1; k += 4) {
            double2 hh = *(const double2*)(hp + k);
            u64 h01 = __double_as_longlong(hh.x);
            u64 h23 = __double_as_longlong(hh.y);
            double2 w1 = *(const double2*)(wr + k);
            ffma2(sr0, h01, __double_as_longlong(w1.x));
            ffma2(sr1, h23, __double_as_longlong(w1.y));
            double2 w2 = *(const double2*)(wz + k);
            ffma2(sz0, h01, __double_as_longlong(w2.x));
            ffma2(sz1, h23, __double_as_longlong(w2.y));
            double2 w3 = *(const double2*)(wn + k);
            ffma2(sn0, h01, __double_as_longlong(w3.x));
            ffma2(sn1, h23, __double_as_longlong(w3.y));
        }
        float ar = unpack_sum(sr0) + unpack_sum(sr1);
        float az = unpack_sum(sz0) + unpack_sum(sz1);
        float an = unpack_sum(sn0) + unpack_sum(sn1);
        size_t rowo = ((size_t)(l*TT + t))*G1;
        const float* xra = xia + rowo;
        const float* xrb = xib + rowo;
        float xr = xra[j] + xrb[j];
        float xz = xra[HID1+j] + xrb[HID1+j];
        float xn = xra[2*HID1+j] + xrb[2*HID1+j];
        float r = 1.f/(1.f + expf(-(xr + ar + cr)));
        float z = 1.f/(1.f + expf(-(xz + az + cz)));
        float n = tanhf(xn + bin + r*(an + bhn));
        float hn = (1.f - z)*n + z*hp[j];
        __stcg(hout + l*HID1 + j, hn);
        if (t < TT-1) {
            int epoch = t + 1;
            __threadfence();
            __syncthreads();
            if (w == 0) {
                int last = 0;
                if (l == 0) last = (atomicAdd(&g_cnt1, 1) == NB1 - 1) ? 1 : 0;
                last = __shfl_sync(0xffffffffu, last, 0);
                if (last) {
                    if (l == 0) { g_cnt1 = 0; __threadfence(); }
                    __syncwarp();
                    #pragma unroll
                    for (int i = 0; i < NB1/32; ++i)
                        g_rel1[(l + 32*i)*8] = epoch;
                } else if (l == 0) {
                    while (g_rel1[blk*8] < epoch) { }
                    __threadfence();
                }
            }
            __syncthreads();
        }
    }
}

// ---------------- Wi2 column prefix sums ----------------
__global__ void k_prefix(const float* __restrict__ Wi2, float* __restrict__ P) {
    int g = blockIdx.x*blockDim.x + threadIdx.x;
    if (g >= G2) return;
    float acc = 0.f;
    P[g] = 0.f;
    const float* wrow = Wi2 + (size_t)g*HID1;
    for (int d = 0; d < HID1; ++d) {
        acc += wrow[d];
        P[(d+1)*G2 + g] = acc;
    }
}

// ---------------- xi2 via piecewise-constant hrep ----------------
__global__ void __launch_bounds__(480) k_xi2seg(const float* __restrict__ hend,
                                                const float* __restrict__ P,
                                                const float* __restrict__ bi2,
                                                float* __restrict__ xi2) {
    int row = blockIdx.x;
    int b = row / TT, t = row - b*TT;
    int g = threadIdx.x;
    if (g >= G2) return;
    int s0 = HID1*t;
    int q  = s0 / TT;
    float acc = bi2[g];
    float Plo = P[0*G2 + g];
    int d = 0;
    while (d < HID1) {
        int dend = (q+1)*TT - s0;
        if (dend > HID1) dend = HID1;
        float Phi = P[(size_t)dend*G2 + g];
        acc += hend[b*HID1 + q] * (Phi - Plo);
        Plo = Phi;
        d = dend;
        ++q;
    }
    xi2[(size_t)row*G2 + g] = acc;
}

// ---------------- small helpers ----------------
__global__ void k_padWfc(const float* __restrict__ Wfc, float* __restrict__ WfcP) {
    int i = blockIdx.x*blockDim.x + threadIdx.x;
    if (i >= NN*DECS) return;
    int r = i / DECS, c = i - r*DECS;
    WfcP[i] = (c < RHID2) ? Wfc[r*RHID2 + c] : 0.f;
}
__global__ void k_init(float* __restrict__ h0) {
    int i = blockIdx.x*blockDim.x + threadIdx.x;
    if (i < BB*HID1) h0[i] = 0.f;
    if (i < NB1*8) g_rel1[i] = 0;
    if (i == 0) g_cnt1 = 0;
}

// ---------------- GRU2: r,z weights in smem (182KB), n-gate streamed ----------------
__global__ void __launch_bounds__(512) k_gru2(const float* __restrict__ xi2,
                                              const float* __restrict__ Wh2,
                                              const float* __restrict__ bh2,
                                              float* __restrict__ dec) {
    extern __shared__ float smw[];      // [150][304]
    __shared__ float h[RHID2];
    __shared__ float rg[RHID2], zg[RHID2], ng_[RHID2];
    int b = blockIdx.x, tid = threadIdx.x;
    int g = tid / 160, u = tid - g*160;
    bool active = (g < 3) && (u < RHID2);
    for (int i = tid; i < RHID2*304; i += 512) {
        int k = i / 304, q = i - k*304;
        int gg = q / 152, uu = q - gg*152;
        smw[i] = (uu < RHID2) ? Wh2[(gg*RHID2 + uu)*RHID2 + k] : 0.f;
    }
    float bias = active ? bh2[g*RHID2 + u] : 0.f;
    if (tid < RHID2) h[tid] = 0.f;
    const float* wn_row = Wh2 + (size_t)(2*RHID2 + (active ? u : 0))*RHID2;
    __syncthreads();

    for (int t = 0; t < TT; ++t) {
        int row = b*TT + t;
        if (active) {
            if (g < 2) {
                const float* wc = smw + g*152 + u;
                float acc = 0.f;
                #pragma unroll 6
                for (int k = 0; k < RHID2; ++k)
                    acc += wc[k*304] * h[k];
                float x = xi2[(size_t)row*G2 + g*RHID2 + u];
                float val = 1.f/(1.f + expf(-(x + acc + bias)));
                if (g == 0) rg[u] = val; else zg[u] = val;
            } else {
                float a0 = 0.f, a1 = 0.f;
                #pragma unroll 5
                for (int k = 0; k < RHID2; k += 2) {
                    float2 w2 = *(const float2*)(wn_row + k);
                    a0 += w2.x * h[k];
                    a1 += w2.y * h[k+1];
                }
                ng_[u] = a0 + a1 + bias;
            }
        }
        __syncthreads();
        if (tid < RHID2) {
            float xn = xi2[(size_t)row*G2 + 2*RHID2 + tid];
            float n = tanhf(xn + rg[tid]*ng_[tid]);
            float hn = (1.f - zg[tid])*n + zg[tid]*h[tid];
            h[tid] = hn;
            dec[(size_t)row*DECS + tid] = hn;
        }
        __syncthreads();
    }
}

// ---------------- launch ----------------
extern "C" void kernel_launch(void* const* d_in, const int* in_sizes, int n_in,
                              void* d_out, int out_size) {
    const float* window = (const float*)d_in[0];
    const float* emb    = (const float*)d_in[1];
    const float* w_init = (const float*)d_in[2];
    const float* w_root = (const float*)d_in[3];
    const float* arma_b = (const float*)d_in[4];
    const float* Wi1    = (const float*)d_in[5];
    const float* Wh1    = (const float*)d_in[6];
    const float* bi1    = (const float*)d_in[7];
    const float* bh1    = (const float*)d_in[8];
    const float* Wi2    = (const float*)d_in[9];
    const float* Wh2    = (const float*)d_in[10];
    const float* bi2    = (const float*)d_in[11];
    const float* bh2    = (const float*)d_in[12];
    const float* W_fc   = (const float*)d_in[13];
    const float* b_fc   = (const float*)d_in[14];
    float* out = (float*)d_out;

    float *Mt, *xi1a, *xi1b, *hbase, *Pm, *xi2, *dec, *WfcP;
    __nv_bfloat16 *Ahi, *Alo, *Bhi, *Blo;
    cudaGetSymbolAddress((void**)&Mt,    g_Mt);
    cudaGetSymbolAddress((void**)&Ahi,   g_Ahi);
    cudaGetSymbolAddress((void**)&Alo,   g_Alo);
    cudaGetSymbolAddress((void**)&Bhi,   g_Bhi);
    cudaGetSymbolAddress((void**)&Blo,   g_Blo);
    cudaGetSymbolAddress((void**)&xi1a,  g_xi1a);
    cudaGetSymbolAddress((void**)&xi1b,  g_xi1b);
    cudaGetSymbolAddress((void**)&hbase, g_h);
    cudaGetSymbolAddress((void**)&Pm,    g_P);
    cudaGetSymbolAddress((void**)&xi2,   g_xi2);
    cudaGetSymbolAddress((void**)&dec,   g_dec);
    cudaGetSymbolAddress((void**)&WfcP,  g_WfcP);
    float* hb0 = hbase;
    float* hb1 = hbase + BB*HID1;

    const int smem_gemm = 3*32768 + 1024;
    const int smem_gru1 = (4*3*HID1 + BB*516) * 4;
    const int smem_gru2 = RHID2*304*4;
    cudaFuncSetAttribute(gemm_mma, cudaFuncAttributeMaxDynamicSharedMemorySize, smem_gemm);
    cudaFuncSetAttribute(gru1_persist, cudaFuncAttributeMaxDynamicSharedMemorySize, smem_gru1);
    cudaFuncSetAttribute(k_gru2, cudaFuncAttributeMaxDynamicSharedMemorySize, smem_gru2);

    k_graph<<<1, 512>>>(emb, Mt);
    k_convW<<<(int)(((size_t)G1*DIN + 255)/256), 256>>>(Wi1, Bhi, Blo);
    k_arma<<<ROWS, 160>>>(window, emb, w_init, w_root, arma_b, Mt, Ahi, Alo);

    gemm_mma<<<dim3(G1/128, ROWS/128, KSPLIT), 256, smem_gemm>>>(Ahi, Alo, Bhi, Blo, xi1a, xi1b);

    k_init<<<(BB*HID1 + 255)/256, 256>>>(hb0);
    gru1_persist<<<NB1, 128, smem_gru1>>>(xi1a, xi1b, Wh1, bi1, bh1, hb0, hb1);
    // final h in hb0

    k_prefix<<<(G2 + 127)/128, 128>>>(Wi2, Pm);
    k_xi2seg<<<ROWS, 480>>>(hb0, Pm, bi2, xi2);

    k_gru2<<<BB, 512, smem_gru2>>>(xi2, Wh2, bh2, dec);

    k_padWfc<<<(NN*DECS + 255)/256, 256>>>(W_fc, WfcP);
    gemm_nt_bias<<<dim3((NN+127)/128, (ROWS+127)/128), 256>>>(dec, WfcP, b_fc, out,
                                                              ROWS, NN, RHID2, DECS, DECS, NN);
}

// round 16
// speedup vs baseline: 1.0452x; 1.0452x over previous
#include <cuda_runtime.h>
#include <cuda_bf16.h>
#include <math.h>
#include <stdint.h>

#define BB 32
#define TT 100
#define NN 150
#define CHN 32
#define HID1 512
#define RHID2 150
#define DIN (NN*CHN)        // 4800
#define G1 (3*HID1)         // 1536
#define G2 (3*RHID2)        // 450
#define ROWS (BB*TT)        // 3200
#define TOPK 10
#define DECS 152
#define NB1 128
#define KSPLIT 2
#define CH_PER 75

typedef unsigned long long u64;

// ---------------- scratch ----------------
__device__ __align__(256) float g_Mt[NN*NN];
__device__ __align__(256) __nv_bfloat16 g_Ahi[(size_t)ROWS*DIN];
__device__ __align__(256) __nv_bfloat16 g_Alo[(size_t)ROWS*DIN];
__device__ __align__(256) __nv_bfloat16 g_Bhi[(size_t)G1*DIN];
__device__ __align__(256) __nv_bfloat16 g_Blo[(size_t)G1*DIN];
__device__ __align__(256) float g_xi1a[(size_t)ROWS*G1];   // layout [col][t][b]
__device__ __align__(256) float g_xi1b[(size_t)ROWS*G1];   // layout [col][t][b]
__device__ __align__(256) float g_h[2*BB*HID1];
__device__ __align__(256) float g_P[(HID1+1)*G2];
__device__ __align__(256) float g_xi2[(size_t)ROWS*G2];
__device__ __align__(256) float g_dec[(size_t)ROWS*DECS];
__device__ __align__(256) float g_WfcP[NN*DECS];
__device__ int g_c1[32*8];          // stage-1 counters (padded)
__device__ int g_c2;                // stage-2 counter
__device__ volatile int g_rel1[NB1*8];

__device__ __forceinline__ uint32_t smem_u32(const void* p) {
    uint32_t a;
    asm("{ .reg .u64 t; cvta.to.shared.u64 t, %1; cvt.u32.u64 %0, t; }" : "=r"(a) : "l"(p));
    return a;
}
__device__ __forceinline__ void ldsm_x4(uint32_t* r, uint32_t addr) {
    asm volatile("ldmatrix.sync.aligned.m8n8.x4.shared.b16 {%0,%1,%2,%3}, [%4];"
        : "=r"(r[0]), "=r"(r[1]), "=r"(r[2]), "=r"(r[3]) : "r"(addr));
}
__device__ __forceinline__ void mma16816(float* c, const uint32_t* a, const uint32_t* b) {
    asm volatile("mma.sync.aligned.m16n8k16.row.col.f32.bf16.bf16.f32 "
        "{%0,%1,%2,%3}, {%4,%5,%6,%7}, {%8,%9}, {%0,%1,%2,%3};"
        : "+f"(c[0]), "+f"(c[1]), "+f"(c[2]), "+f"(c[3])
        : "r"(a[0]), "r"(a[1]), "r"(a[2]), "r"(a[3]), "r"(b[0]), "r"(b[1]));
}
__device__ __forceinline__ uint32_t sw64(uint32_t off) {
    return off ^ ((off >> 3) & 0x30);
}
__device__ __forceinline__ void cp16(uint32_t s, const void* g) {
    asm volatile("cp.async.cg.shared.global [%0], [%1], 16;" :: "r"(s), "l"(g));
}
#define CP_COMMIT() asm volatile("cp.async.commit_group;" ::: "memory")
#define CP_WAIT(n)  asm volatile("cp.async.wait_group %0;" :: "n"(n) : "memory")
__device__ __forceinline__ void ffma2(u64& d, u64 a, u64 b) {
    asm("fma.rn.f32x2 %0, %1, %2, %0;" : "+l"(d) : "l"(a), "l"(b));
}
__device__ __forceinline__ float unpack_sum(u64 v) {
    float x, y;
    asm("mov.b64 {%0,%1}, %2;" : "=f"(x), "=f"(y) : "l"(v));
    return x + y;
}

// ---------------- graph construction (512 threads) ----------------
__global__ void k_graph(const float* __restrict__ emb, float* __restrict__ Mt) {
    __shared__ float Wn[NN][CHN];
    __shared__ float rowbuf[16][NN+2];
    __shared__ int   eidx[NN*TOPK];
    __shared__ float eval_[NN*TOPK];
    __shared__ float deg[NN];
    __shared__ float dinv[NN];
    int tid = threadIdx.x;
    for (int i = tid; i < NN; i += blockDim.x) {
        float s = 0.f;
        for (int c = 0; c < CHN; c++) { float v = emb[i*CHN+c]; s += v*v; }
        float inv = 1.f/fmaxf(sqrtf(s), 1e-8f);
        for (int c = 0; c < CHN; c++) Wn[i][c] = emb[i*CHN+c]*inv;
    }
    for (int i = tid; i < NN; i += blockDim.x) deg[i] = 0.f;
    __syncthreads();
    int w = tid >> 5, l = tid & 31;
    for (int i = w; i < NN; i += 16) {
        for (int j = l; j < NN; j += 32) {
            float s = 0.f;
            #pragma unroll
            for (int c = 0; c < CHN; c++) s += Wn[i][c]*Wn[j][c];
            if (j == i) s = 0.f;
            rowbuf[w][j] = fmaxf(s, 0.f);
        }
        __syncwarp();
        for (int rep = 0; rep < TOPK; rep++) {
            float bv = -2.f; int bi = 1<<30;
            for (int j = l; j < NN; j += 32) {
                float v = rowbuf[w][j];
                if (v > bv) { bv = v; bi = j; }
            }
            for (int off = 16; off; off >>= 1) {
                float ov = __shfl_down_sync(0xffffffffu, bv, off);
                int   oi = __shfl_down_sync(0xffffffffu, bi, off);
                if (ov > bv || (ov == bv && oi < bi)) { bv = ov; bi = oi; }
            }
            bv = __shfl_sync(0xffffffffu, bv, 0);
            bi = __shfl_sync(0xffffffffu, bi, 0);
            if (l == 0) {
                eidx[i*TOPK+rep] = bi;
                eval_[i*TOPK+rep] = bv;
                rowbuf[w][bi] = -1.f;
            }
            __syncwarp();
        }
    }
    __syncthreads();
    for (int e = tid; e < NN*TOPK; e += blockDim.x)
        atomicAdd(&deg[eidx[e]], eval_[e]);
    __syncthreads();
    for (int i = tid; i < NN; i += blockDim.x)
        dinv[i] = deg[i] > 0.f ? 1.f/sqrtf(deg[i]) : 0.f;
    for (int i = tid; i < NN*NN; i += blockDim.x) Mt[i] = 0.f;
    __syncthreads();
    for (int e = tid; e < NN*TOPK; e += blockDim.x) {
        int src = e / TOPK;
        int dst = eidx[e];
        Mt[src*NN + dst] = dinv[src]*eval_[e]*dinv[dst];
    }
}

// ---------------- ARMA conv + gelu + emb -> bf16 hi/lo (perm fused in) --------------
__global__ void k_arma(const float* __restrict__ window, const float* __restrict__ emb,
                       const float* __restrict__ w_init, const float* __restrict__ w_root,
                       const float* __restrict__ arma_b, const float* __restrict__ Mt,
                       __nv_bfloat16* __restrict__ Ahi, __nv_bfloat16* __restrict__ Alo) {
    __shared__ float xs[NN];
    __shared__ float s[NN];
    __shared__ int rowbase[NN];
    __shared__ int embbase[NN];
    int blk = blockIdx.x;
    int base = blk*NN;
    int tid = threadIdx.x;
    for (int i = tid; i < NN; i += blockDim.x) {
        int f = base + i;
        int bx  = f / (NN*TT);
        int rem = f - bx*(NN*TT);
        int nx  = rem / TT;
        int tx2 = rem - nx*TT;
        xs[i] = window[(bx*TT + tx2)*NN + nx];
        rowbase[i] = (bx*TT + tx2)*DIN + nx*CHN;
        embbase[i] = nx*CHN;
    }
    __syncthreads();
    for (int n = tid; n < NN; n += blockDim.x) {
        float acc = 0.f;
        #pragma unroll 5
        for (int m = 0; m < NN; m++) acc += Mt[m*NN+n]*xs[m];
        s[n] = acc;
    }
    __syncthreads();
    for (int i = tid; i < DIN; i += blockDim.x) {
        int n = i >> 5, c = i & 31;
        float v = s[n]*w_init[c] + xs[n]*w_root[c] + arma_b[c];
        float g = 0.5f*v*(1.f + erff(v*0.70710678118654752f));
        float val = g + emb[embbase[n] + c];
        __nv_bfloat16 hi = __float2bfloat16(val);
        float lo = val - __bfloat162float(hi);
        size_t idx = (size_t)rowbase[n] + c;
        Ahi[idx] = hi;
        Alo[idx] = __float2bfloat16(lo);
    }
}

// ---------------- Wi1 fp32 -> bf16 hi/lo split ----------------
__global__ void k_convW(const float* __restrict__ Wi1,
                        __nv_bfloat16* __restrict__ Bhi, __nv_bfloat16* __restrict__ Blo) {
    size_t i = (size_t)blockIdx.x*blockDim.x + threadIdx.x;
    if (i >= (size_t)G1*DIN) return;
    float v = Wi1[i];
    __nv_bfloat16 hi = __float2bfloat16(v);
    Bhi[i] = hi;
    Blo[i] = __float2bfloat16(v - __bfloat162float(hi));
}

// ---------------- mma.sync bf16-split GEMM: split-K x2, transposed [col][t][b] out ---
__global__ void __launch_bounds__(256, 2) gemm_mma(
    const __nv_bfloat16* __restrict__ Ahi, const __nv_bfloat16* __restrict__ Alo,
    const __nv_bfloat16* __restrict__ Bhi, const __nv_bfloat16* __restrict__ Blo,
    float* __restrict__ C0, float* __restrict__ C1) {
    extern __shared__ char dsm[];
    int tid = threadIdx.x, wid = tid >> 5, lane = tid & 31;
    int bm = blockIdx.y*128, bn = blockIdx.x*128;
    int cbeg = blockIdx.z*CH_PER;
    int wm = (wid & 3)*32;
    int wn = (wid >> 2)*64;

    uint32_t dbase = smem_u32(dsm);
    uint32_t pad = (1024u - (dbase & 1023u)) & 1023u;
    uint32_t tb = dbase + pad;

    float acc[2][8][4];
    #pragma unroll
    for (int i = 0; i < 2; i++)
        #pragma unroll
        for (int j = 0; j < 8; j++)
            #pragma unroll
            for (int q = 0; q < 4; q++) acc[i][j][q] = 0.f;

    int a_row = (lane & 15);
    int a_kc  = (lane >= 16) ? 8 : 0;
    int b_n   = (lane & 7) + ((lane & 16) ? 8 : 0);
    int b_kc  = (lane & 8) ? 8 : 0;

    int l_row[2], l_q[2];
    #pragma unroll
    for (int it = 0; it < 2; ++it) {
        int idx = it*256 + tid;
        l_row[it] = idx >> 2;
        l_q[it]   = idx & 3;
    }

    #define LOAD_STAGE(ca, s) do {                                         \
        uint32_t sb_ = tb + (s)*32768;                                     \
        int c0_ = (ca)*32;                                                 \
        _Pragma("unroll")                                                  \
        for (int it = 0; it < 2; ++it) {                                   \
            uint32_t sw_ = sw64(l_row[it]*64 + l_q[it]*16);                \
            size_t ga_ = (size_t)(bm + l_row[it])*DIN + c0_ + l_q[it]*8;   \
            size_t gb_ = (size_t)(bn + l_row[it])*DIN + c0_ + l_q[it]*8;   \
            cp16(sb_ + sw_,         Ahi + ga_);                            \
            cp16(sb_ + 8192 + sw_,  Alo + ga_);                            \
            cp16(sb_ + 16384 + sw_, Bhi + gb_);                            \
            cp16(sb_ + 24576 + sw_, Blo + gb_);                            \
        }                                                                  \
        CP_COMMIT();                                                       \
    } while (0)

    LOAD_STAGE(cbeg + 0, 0);
    LOAD_STAGE(cbeg + 1, 1);
    for (int c = 0; c < CH_PER; ++c) {
        if (c + 2 < CH_PER) { LOAD_STAGE(cbeg + c + 2, (c+2)%3); CP_WAIT(2); }
        else if (c + 1 < CH_PER) CP_WAIT(1);
        else CP_WAIT(0);
        __syncthreads();
        uint32_t sb = tb + (c%3)*32768;
        uint32_t apass[3] = { sb, sb, sb + 8192 };
        uint32_t bpass[3] = { sb + 16384, sb + 24576, sb + 16384 };
        #pragma unroll
        for (int p = 0; p < 3; ++p) {
            uint32_t aT = apass[p], bT = bpass[p];
            #pragma unroll
            for (int ks = 0; ks < 2; ++ks) {
                uint32_t af[2][4];
                #pragma unroll
                for (int mh = 0; mh < 2; ++mh) {
                    int row = wm + mh*16 + a_row;
                    int kc = ks*16 + a_kc;
                    ldsm_x4(af[mh], aT + sw64(row*64 + kc*2));
                }
                uint32_t bf[4][4];
                #pragma unroll
                for (int q = 0; q < 4; ++q) {
                    int n = wn + q*16 + b_n;
                    int kc = ks*16 + b_kc;
                    ldsm_x4(bf[q], bT + sw64(n*64 + kc*2));
                }
                #pragma unroll
                for (int mh = 0; mh < 2; ++mh)
                    #pragma unroll
                    for (int q = 0; q < 4; ++q) {
                        mma16816(acc[mh][2*q],   af[mh], &bf[q][0]);
                        mma16816(acc[mh][2*q+1], af[mh], &bf[q][2]);
                    }
            }
        }
        __syncthreads();
    }

    // epilogue: scatter to transposed layout [col][t][b]
    float* C = blockIdx.z ? C1 : C0;
    #pragma unroll
    for (int mh = 0; mh < 2; ++mh) {
        int row0 = bm + wm + mh*16 + (lane >> 2);
        int b0 = row0 / TT, t0 = row0 - b0*TT;
        int row1 = row0 + 8;
        int b1 = row1 / TT, t1 = row1 - b1*TT;
        #pragma unroll
        for (int nb = 0; nb < 8; ++nb) {
            int col = bn + wn + nb*8 + (lane & 3)*2;
            C[((size_t)col*TT + t0)*BB + b0]       = acc[mh][nb][0];
            C[((size_t)(col+1)*TT + t0)*BB + b0]   = acc[mh][nb][1];
            C[((size_t)col*TT + t1)*BB + b1]       = acc[mh][nb][2];
            C[((size_t)(col+1)*TT + t1)*BB + b1]   = acc[mh][nb][3];
        }
    }
}

// ---------------- generic SIMT NT GEMM (final fc) ----------------
__global__ void gemm_nt_bias(const float* __restrict__ A, const float* __restrict__ Bm,
                             const float* __restrict__ bias, float* __restrict__ C,
                             int M, int N, int K, int lda, int ldb, int ldc) {
    __shared__ float As[16][132];
    __shared__ float Bs[16][132];
    const int tid = threadIdx.x;
    const int tx = tid & 15, ty = tid >> 4;
    const int bm = blockIdx.y * 128, bn = blockIdx.x * 128;
    float acc[8][8];
    #pragma unroll
    for (int i = 0; i < 8; i++)
        #pragma unroll
        for (int j = 0; j < 8; j++) acc[i][j] = 0.f;
    for (int k0 = 0; k0 < K; k0 += 16) {
        #pragma unroll
        for (int q = 0; q < 2; q++) {
            int idx = tid + q*256;
            int row = idx >> 2;
            int c4  = (idx & 3) << 2;
            int gk = k0 + c4;
            float4 va = make_float4(0.f,0.f,0.f,0.f);
            float4 vb = make_float4(0.f,0.f,0.f,0.f);
            int ga = bm + row, gb = bn + row;
            if (ga < M && gk < K) {
                const float* p = A + (size_t)ga*lda;
                if (gk + 3 < K) va = *(const float4*)(p + gk);
                else {
                    va.x = p[gk];
                    if (gk+1 < K) va.y = p[gk+1];
                    if (gk+2 < K) va.z = p[gk+2];
                }
            }
            if (gb < N && gk < K) {
                const float* p = Bm + (size_t)gb*ldb;
                if (gk + 3 < K) vb = *(const float4*)(p + gk);
                else {
                    vb.x = p[gk];
                    if (gk+1 < K) vb.y = p[gk+1];
                    if (gk+2 < K) vb.z = p[gk+2];
                }
            }
            As[c4+0][row]=va.x; As[c4+1][row]=va.y; As[c4+2][row]=va.z; As[c4+3][row]=va.w;
            Bs[c4+0][row]=vb.x; Bs[c4+1][row]=vb.y; Bs[c4+2][row]=vb.z; Bs[c4+3][row]=vb.w;
        }
        __syncthreads();
        #pragma unroll
        for (int kk = 0; kk < 16; kk++) {
            float4 a0 = *(const float4*)&As[kk][ty*4];
            float4 a1 = *(const float4*)&As[kk][64 + ty*4];
            float4 b0 = *(const float4*)&Bs[kk][tx*4];
            float4 b1 = *(const float4*)&Bs[kk][64 + tx*4];
            float a[8] = {a0.x,a0.y,a0.z,a0.w,a1.x,a1.y,a1.z,a1.w};
            float b[8] = {b0.x,b0.y,b0.z,b0.w,b1.x,b1.y,b1.z,b1.w};
            #pragma unroll
            for (int i = 0; i < 8; i++)
                #pragma unroll
                for (int j = 0; j < 8; j++) acc[i][j] += a[i]*b[j];
        }
        __syncthreads();
    }
    #pragma unroll
    for (int i = 0; i < 8; i++) {
        int gm = bm + ((i < 4) ? ty*4+i : 64+ty*4+(i-4));
        if (gm >= M) continue;
        #pragma unroll
        for (int j = 0; j < 8; j++) {
            int gn = bn + ((j < 4) ? tx*4+j : 64+tx*4+(j-4));
            if (gn < N) C[(size_t)gm*ldc + gn] = acc[i][j] + bias[gn];
        }
    }
}

// ---------------- persistent GRU1: coalesced xT loads, barrier tree ----------------
__global__ void __launch_bounds__(128) gru1_persist(
    const float* __restrict__ xia, const float* __restrict__ xib,
    const float* __restrict__ Wh1, const float* __restrict__ bi1,
    const float* __restrict__ bh1, float* __restrict__ h0, float* __restrict__ h1) {
    extern __shared__ float sm[];
    float* ws = sm;
    float* hs = sm + 4*3*HID1;
    const int STR = 516;
    int tid = threadIdx.x, w = tid >> 5, l = tid & 31, blk = blockIdx.x;
    int j = blk*4 + w;

    for (int g = 0; g < 3; ++g) {
        const float* src = Wh1 + ((size_t)(g*HID1 + j))*HID1;
        for (int k = l*4; k < HID1; k += 128)
            *(float4*)&ws[(w*3+g)*HID1 + k] = *(const float4*)(src + k);
    }
    float cr = bi1[j] + bh1[j];
    float cz = bi1[HID1+j] + bh1[HID1+j];
    float bin = bi1[2*HID1+j];
    float bhn = bh1[2*HID1+j];
    // transposed x pointers: [col][t][b], lanes (b) consecutive
    const float* xar = xia + (size_t)j*TT*BB + l;
    const float* xaz = xia + (size_t)(HID1+j)*TT*BB + l;
    const float* xan = xia + (size_t)(2*HID1+j)*TT*BB + l;
    const float* xbr = xib + (size_t)j*TT*BB + l;
    const float* xbz = xib + (size_t)(HID1+j)*TT*BB + l;
    const float* xbn = xib + (size_t)(2*HID1+j)*TT*BB + l;
    __syncthreads();

    float* hb[2] = { h0, h1 };
    for (int t = 0; t < TT; ++t) {
        const float* hin = hb[t & 1];
        float* hout = hb[(t+1) & 1];
        for (int i = tid; i < BB*(HID1/4); i += 128) {
            int b = i >> 7, k4 = (i & 127) << 2;
            float4 v = __ldcg((const float4*)(hin + b*HID1 + k4));
            *(float4*)&hs[b*STR + k4] = v;
        }
        __syncthreads();
        const float* wr = &ws[(w*3+0)*HID1];
        const float* wz = &ws[(w*3+1)*HID1];
        const float* wn = &ws[(w*3+2)*HID1];
        const float* hp = &hs[l*STR];
        u64 sr0 = 0, sr1 = 0, sz0 = 0, sz1 = 0, sn0 = 0, sn1 = 0;
        #pragma unroll 8
        for (int k = 0; k < HID1; k += 4) {
            double2 hh = *(const double2*)(hp + k);
            u64 h01 = __double_as_longlong(hh.x);
            u64 h23 = __double_as_longlong(hh.y);
            double2 w1 = *(const double2*)(wr + k);
            ffma2(sr0, h01, __double_as_longlong(w1.x));
            ffma2(sr1, h23, __double_as_longlong(w1.y));
            double2 w2 = *(const double2*)(wz + k);
            ffma2(sz0, h01, __double_as_longlong(w2.x));
            ffma2(sz1, h23, __double_as_longlong(w2.y));
            double2 w3 = *(const double2*)(wn + k);
            ffma2(sn0, h01, __double_as_longlong(w3.x));
            ffma2(sn1, h23, __double_as_longlong(w3.y));
        }
        float ar = unpack_sum(sr0) + unpack_sum(sr1);
        float az = unpack_sum(sz0) + unpack_sum(sz1);
        float an = unpack_sum(sn0) + unpack_sum(sn1);
        int to = t*BB;
        float xr = xar[to] + xbr[to];
        float xz = xaz[to] + xbz[to];
        float xn = xan[to] + xbn[to];
        float r = 1.f/(1.f + expf(-(xr + ar + cr)));
        float z = 1.f/(1.f + expf(-(xz + az + cz)));
        float n = tanhf(xn + bin + r*(an + bhn));
        float hn = (1.f - z)*n + z*hp[j];
        __stcg(hout + l*HID1 + j, hn);
        if (t < TT-1) {
            int epoch = t + 1;
            __threadfence();
            __syncthreads();
            if (w == 0) {
                int last = 0;
                if (l == 0) {
                    int o1 = atomicAdd(&g_c1[(blk & 31)*8], 1);
                    if (((o1 + 1) & 3) == 0) {              // last of the 4 blocks in group
                        int o2 = atomicAdd(&g_c2, 1);
                        if (((o2 + 1) & 7) == 0) last = 1;  // overall last of 32 groups' reps (8/epoch)
                    }
                }
                last = __shfl_sync(0xffffffffu, last, 0);
                if (last) {
                    __threadfence();
                    #pragma unroll
                    for (int i = 0; i < NB1/32; ++i)
                        g_rel1[(l + 32*i)*8] = epoch;
                } else if (l == 0) {
                    while (g_rel1[blk*8] < epoch) { }
                    __threadfence();
                }
            }
            __syncthreads();
        }
    }
}

// ---------------- Wi2 column prefix sums: warp per gate-column, shuffle scan --------
__global__ void k_prefix(const float* __restrict__ Wi2, float* __restrict__ P) {
    int gw = blockIdx.x*4 + (threadIdx.x >> 5);
    int l = threadIdx.x & 31;
    if (gw >= G2) return;
    const float* wrow = Wi2 + (size_t)gw*HID1;
    if (l == 0) P[gw] = 0.f;
    float carry = 0.f;
    #pragma unroll
    for (int c = 0; c < HID1/32; ++c) {
        float v = wrow[c*32 + l];
        #pragma unroll
        for (int off = 1; off < 32; off <<= 1) {
            float nv = __shfl_up_sync(0xffffffffu, v, off);
            if (l >= off) v += nv;
        }
        P[(size_t)(c*32 + l + 1)*G2 + gw] = v + carry;
        carry += __shfl_sync(0xffffffffu, v, 31);
    }
}

// ---------------- xi2 via piecewise-constant hrep ----------------
__global__ void __launch_bounds__(480) k_xi2seg(const float* __restrict__ hend,
                                                const float* __restrict__ P,
                                                const float* __restrict__ bi2,
                                                float* __restrict__ xi2) {
    int row = blockIdx.x;
    int b = row / TT, t = row - b*TT;
    int g = threadIdx.x;
    if (g >= G2) return;
    int s0 = HID1*t;
    int q  = s0 / TT;
    float acc = bi2[g];
    float Plo = P[0*G2 + g];
    int d = 0;
    while (d < HID1) {
        int dend = (q+1)*TT - s0;
        if (dend > HID1) dend = HID1;
        float Phi = P[(size_t)dend*G2 + g];
        acc += hend[b*HID1 + q] * (Phi - Plo);
        Plo = Phi;
        d = dend;
        ++q;
    }
    xi2[(size_t)row*G2 + g] = acc;
}

// ---------------- small helpers ----------------
__global__ void k_padWfc(const float* __restrict__ Wfc, float* __restrict__ WfcP) {
    int i = blockIdx.x*blockDim.x + threadIdx.x;
    if (i >= NN*DECS) return;
    int r = i / DECS, c = i - r*DECS;
    WfcP[i] = (c < RHID2) ? Wfc[r*RHID2 + c] : 0.f;
}
__global__ void k_init(float* __restrict__ h0) {
    int i = blockIdx.x*blockDim.x + threadIdx.x;
    if (i < BB*HID1) h0[i] = 0.f;
    if (i < NB1*8) g_rel1[i] = 0;
    if (i < 32*8) g_c1[i] = 0;
    if (i == 0) g_c2 = 0;
}

// ---------------- GRU2: r,z weights in smem (182KB), n-gate streamed ----------------
__global__ void __launch_bounds__(512) k_gru2(const float* __restrict__ xi2,
                                              const float* __restrict__ Wh2,
                                              const float* __restrict__ bh2,
                                              float* __restrict__ dec) {
    extern __shared__ float smw[];      // [150][304]
    __shared__ float h[RHID2];
    __shared__ float rg[RHID2], zg[RHID2], ng_[RHID2];
    int b = blockIdx.x, tid = threadIdx.x;
    int g = tid / 160, u = tid - g*160;
    bool active = (g < 3) && (u < RHID2);
    for (int i = tid; i < RHID2*304; i += 512) {
        int k = i / 304, q = i - k*304;
        int gg = q / 152, uu = q - gg*152;
        smw[i] = (uu < RHID2) ? Wh2[(gg*RHID2 + uu)*RHID2 + k] : 0.f;
    }
    float bias = active ? bh2[g*RHID2 + u] : 0.f;
    if (tid < RHID2) h[tid] = 0.f;
    const float* wn_row = Wh2 + (size_t)(2*RHID2 + (active ? u : 0))*RHID2;
    __syncthreads();

    for (int t = 0; t < TT; ++t) {
        int row = b*TT + t;
        if (active) {
            if (g < 2) {
                const float* wc = smw + g*152 + u;
                float acc = 0.f;
                #pragma unroll 6
                for (int k = 0; k < RHID2; ++k)
                    acc += wc[k*304] * h[k];
                float x = xi2[(size_t)row*G2 + g*RHID2 + u];
                float val = 1.f/(1.f + expf(-(x + acc + bias)));
                if (g == 0) rg[u] = val; else zg[u] = val;
            } else {
                float a0 = 0.f, a1 = 0.f;
                #pragma unroll 5
                for (int k = 0; k < RHID2; k += 2) {
                    float2 w2 = *(const float2*)(wn_row + k);
                    a0 += w2.x * h[k];
                    a1 += w2.y * h[k+1];
                }
                ng_[u] = a0 + a1 + bias;
            }
        }
        __syncthreads();
        if (tid < RHID2) {
            float xn = xi2[(size_t)row*G2 + 2*RHID2 + tid];
            float n = tanhf(xn + rg[tid]*ng_[tid]);
            float hn = (1.f - zg[tid])*n + zg[tid]*h[tid];
            h[tid] = hn;
            dec[(size_t)row*DECS + tid] = hn;
        }
        __syncthreads();
    }
}

// ---------------- launch ----------------
extern "C" void kernel_launch(void* const* d_in, const int* in_sizes, int n_in,
                              void* d_out, int out_size) {
    const float* window = (const float*)d_in[0];
    const float* emb    = (const float*)d_in[1];
    const float* w_init = (const float*)d_in[2];
    const float* w_root = (const float*)d_in[3];
    const float* arma_b = (const float*)d_in[4];
    const float* Wi1    = (const float*)d_in[5];
    const float* Wh1    = (const float*)d_in[6];
    const float* bi1    = (const float*)d_in[7];
    const float* bh1    = (const float*)d_in[8];
    const float* Wi2    = (const float*)d_in[9];
    const float* Wh2    = (const float*)d_in[10];
    const float* bi2    = (const float*)d_in[11];
    const float* bh2    = (const float*)d_in[12];
    const float* W_fc   = (const float*)d_in[13];
    const float* b_fc   = (const float*)d_in[14];
    float* out = (float*)d_out;

    float *Mt, *xi1a, *xi1b, *hbase, *Pm, *xi2, *dec, *WfcP;
    __nv_bfloat16 *Ahi, *Alo, *Bhi, *Blo;
    cudaGetSymbolAddress((void**)&Mt,    g_Mt);
    cudaGetSymbolAddress((void**)&Ahi,   g_Ahi);
    cudaGetSymbolAddress((void**)&Alo,   g_Alo);
    cudaGetSymbolAddress((void**)&Bhi,   g_Bhi);
    cudaGetSymbolAddress((void**)&Blo,   g_Blo);
    cudaGetSymbolAddress((void**)&xi1a,  g_xi1a);
    cudaGetSymbolAddress((void**)&xi1b,  g_xi1b);
    cudaGetSymbolAddress((void**)&hbase, g_h);
    cudaGetSymbolAddress((void**)&Pm,    g_P);
    cudaGetSymbolAddress((void**)&xi2,   g_xi2);
    cudaGetSymbolAddress((void**)&dec,   g_dec);
    cudaGetSymbolAddress((void**)&WfcP,  g_WfcP);
    float* hb0 = hbase;
    float* hb1 = hbase + BB*HID1;

    const int smem_gemm = 3*32768 + 1024;
    const int smem_gru1 = (4*3*HID1 + BB*516) * 4;
    const int smem_gru2 = RHID2*304*4;
    cudaFuncSetAttribute(gemm_mma, cudaFuncAttributeMaxDynamicSharedMemorySize, smem_gemm);
    cudaFuncSetAttribute(gru1_persist, cudaFuncAttributeMaxDynamicSharedMemorySize, smem_gru1);
    cudaFuncSetAttribute(k_gru2, cudaFuncAttributeMaxDynamicSharedMemorySize, smem_gru2);

    k_graph<<<1, 512>>>(emb, Mt);
    k_convW<<<(int)(((size_t)G1*DIN + 255)/256), 256>>>(Wi1, Bhi, Blo);
    k_arma<<<ROWS, 160>>>(window, emb, w_init, w_root, arma_b, Mt, Ahi, Alo);

    gemm_mma<<<dim3(G1/128, ROWS/128, KSPLIT), 256, smem_gemm>>>(Ahi, Alo, Bhi, Blo, xi1a, xi1b);

    k_init<<<(BB*HID1 + 255)/256, 256>>>(hb0);
    gru1_persist<<<NB1, 128, smem_gru1>>>(xi1a, xi1b, Wh1, bi1, bh1, hb0, hb1);
    // final h in hb0

    k_prefix<<<(G2 + 3)/4, 128>>>(Wi2, Pm);
    k_xi2seg<<<ROWS, 480>>>(hb0, Pm, bi2, xi2);

    k_gru2<<<BB, 512, smem_gru2>>>(xi2, Wh2, bh2, dec);

    k_padWfc<<<(NN*DECS + 255)/256, 256>>>(W_fc, WfcP);
    gemm_nt_bias<<<dim3((NN+127)/128, (ROWS+127)/128), 256>>>(dec, WfcP, b_fc, out,
                                                              ROWS, NN, RHID2, DECS, DECS, NN);
}